// round 11
// baseline (speedup 1.0000x reference)
#include <cuda_runtime.h>
#include <cuda_bf16.h>
#include <math.h>
#include <stdint.h>
#include <mma.h>

using namespace nvcuda;
typedef __nv_bfloat16 bf16;

#define B_ 1024
#define T_ 16
#define D_ 1024
#define H_ 2048
#define O_ 1024

// ==================== device globals (flat, one symbol per limb) ============
__device__ int   r11_flag, r11_viol;
__device__ float r11_inp[B_ * T_ * H_];
__device__ float r11_pre[B_ * H_];
__device__ float r11_sf[B_ * H_];
__device__ float r11_gf[B_ * H_];
__device__ float r11_ctx[B_ * H_], r11_rec[B_ * H_];
__device__ float r11_attrA[B_ * H_], r11_attrB[B_ * H_];
__device__ float r11_spk[B_ * H_];
__device__ float r11_testF[128 * H_], r11_testT[128 * H_];

__device__ bf16 r11_xb0[B_ * T_ * D_], r11_xb1[B_ * T_ * D_], r11_xb2[B_ * T_ * D_], r11_xb3[B_ * T_ * D_];
__device__ bf16 r11_ib0[B_ * T_ * H_], r11_ib1[B_ * T_ * H_], r11_ib2[B_ * T_ * H_], r11_ib3[B_ * T_ * H_];
__device__ bf16 r11_Wp0[H_ * D_], r11_Wp1[H_ * D_], r11_Wp2[H_ * D_], r11_Wp3[H_ * D_];
__device__ bf16 r11_Wfc0[H_ * H_], r11_Wfc1[H_ * H_], r11_Wfc2[H_ * H_], r11_Wfc3[H_ * H_];
__device__ bf16 r11_Wg0[H_ * H_], r11_Wg1[H_ * H_], r11_Wg2[H_ * H_], r11_Wg3[H_ * H_];
__device__ bf16 r11_We0[H_ * H_], r11_We1[H_ * H_], r11_We2[H_ * H_], r11_We3[H_ * H_];
__device__ bf16 r11_Wr0[H_ * H_], r11_Wr1[H_ * H_], r11_Wr2[H_ * H_], r11_Wr3[H_ * H_];
__device__ bf16 r11_Wo0[O_ * H_], r11_Wo1[O_ * H_], r11_Wo2[O_ * H_], r11_Wo3[O_ * H_];
__device__ bf16 r11_sb0[B_ * H_], r11_sb1[B_ * H_], r11_sb2[B_ * H_], r11_sb3[B_ * H_];
__device__ bf16 r11_gb0[B_ * H_], r11_gb1[B_ * H_], r11_gb2[B_ * H_], r11_gb3[B_ * H_];
__device__ bf16 r11_ab0[B_ * H_], r11_ab1[B_ * H_], r11_ab2[B_ * H_], r11_ab3[B_ * H_];
__device__ bf16 r11_pb0[B_ * H_], r11_pb1[B_ * H_], r11_pb2[B_ * H_], r11_pb3[B_ * H_];

// ==================== helpers ===============================================
__device__ __forceinline__ void r11_split4(float v, bf16* s) {
    s[0] = __float2bfloat16(v);
    float r = v - __bfloat162float(s[0]);
    s[1] = __float2bfloat16(r);
    r -= __bfloat162float(s[1]);
    s[2] = __float2bfloat16(r);
    r -= __bfloat162float(s[2]);
    s[3] = __float2bfloat16(r);
}
__device__ __forceinline__ uint32_t r11_smem_u32(const void* p) {
    uint32_t a;
    asm("{ .reg .u64 t; cvta.to.shared.u64 t, %1; cvt.u32.u64 %0, t; }" : "=r"(a) : "l"(p));
    return a;
}
__device__ __forceinline__ void r11_cp16(uint32_t dst, const void* src) {
    asm volatile("cp.async.cg.shared.global [%0], [%1], 16;" :: "r"(dst), "l"(src));
}

// ==================== fp32 SGEMM (proven engine, gated) =====================
__global__ void __launch_bounds__(256) r11_sgemm(
    const int* gate,
    const float* __restrict__ A1, int lda1, const float* __restrict__ B1,
    const float* __restrict__ A2, int lda2, const float* __restrict__ B2,
    const float* __restrict__ bias1, const float* __restrict__ bias2,
    float* __restrict__ C, int ldc, int M, int N, int K, float alpha)
{
    if (gate && (*(volatile const int*)gate) != 0) return;
    const int BM = 128, BN = 128, BK = 16;
    __shared__ float As[BK][BM];
    __shared__ float Bs[BK][BN];
    const int bm = blockIdx.y * BM, bn = blockIdx.x * BN;
    const int tid = threadIdx.x, tr = tid / 16, tc = tid % 16;
    const int a_r = tid / 4, a_c = (tid % 4) * 4;
    const int b_r = tid / 32, b_c = (tid % 32) * 4;

    float acc[8][8];
#pragma unroll
    for (int i = 0; i < 8; i++)
#pragma unroll
        for (int j = 0; j < 8; j++) acc[i][j] = 0.0f;

    const int npass = (A2 != nullptr) ? 2 : 1;
    for (int pass = 0; pass < npass; pass++) {
        const float* A  = pass ? A2 : A1;
        const float* Bm = pass ? B2 : B1;
        const int lda   = pass ? lda2 : lda1;
        for (int k0 = 0; k0 < K; k0 += BK) {
#pragma unroll
            for (int i = 0; i < 2; i++) {
                int r = a_r + i * 64;
                float4 v = *(const float4*)(A + (long)(bm + r) * lda + k0 + a_c);
                As[a_c + 0][r] = v.x; As[a_c + 1][r] = v.y;
                As[a_c + 2][r] = v.z; As[a_c + 3][r] = v.w;
            }
#pragma unroll
            for (int i = 0; i < 2; i++) {
                int r = b_r + i * 8;
                float4 v = *(const float4*)(Bm + (long)(k0 + r) * N + bn + b_c);
                *(float4*)&Bs[r][b_c] = v;
            }
            __syncthreads();
#pragma unroll
            for (int kk = 0; kk < BK; kk++) {
                float4 a0 = *(const float4*)&As[kk][tr * 8];
                float4 a1 = *(const float4*)&As[kk][tr * 8 + 4];
                float4 b0 = *(const float4*)&Bs[kk][tc * 8];
                float4 b1 = *(const float4*)&Bs[kk][tc * 8 + 4];
                float a[8] = {a0.x, a0.y, a0.z, a0.w, a1.x, a1.y, a1.z, a1.w};
                float b[8] = {b0.x, b0.y, b0.z, b0.w, b1.x, b1.y, b1.z, b1.w};
#pragma unroll
                for (int i = 0; i < 8; i++)
#pragma unroll
                    for (int j = 0; j < 8; j++)
                        acc[i][j] = fmaf(a[i], b[j], acc[i][j]);
            }
            __syncthreads();
        }
    }
    const int row0 = bm + tr * 8, col0 = bn + tc * 8;
    float bias[8];
#pragma unroll
    for (int j = 0; j < 8; j++) {
        float v = bias1 ? bias1[col0 + j] : 0.0f;
        if (bias2) v += bias2[col0 + j];
        bias[j] = v;
    }
#pragma unroll
    for (int i = 0; i < 8; i++) {
        float4 o0, o1;
        o0.x = alpha * acc[i][0] + bias[0]; o0.y = alpha * acc[i][1] + bias[1];
        o0.z = alpha * acc[i][2] + bias[2]; o0.w = alpha * acc[i][3] + bias[3];
        o1.x = alpha * acc[i][4] + bias[4]; o1.y = alpha * acc[i][5] + bias[5];
        o1.z = alpha * acc[i][6] + bias[6]; o1.w = alpha * acc[i][7] + bias[7];
        *(float4*)(C + (long)(row0 + i) * ldc + col0)     = o0;
        *(float4*)(C + (long)(row0 + i) * ldc + col0 + 4) = o1;
    }
}

// ==================== bf16 4-limb tensor GEMM ===============================
#define TBM 128
#define TBN 64
#define TBK 32
#define TLD 40
#define TA_H (TBM * TLD)
#define TB_H (TBN * TLD)
#define TSTAGE (4 * TA_H + 4 * TB_H)
#define TSMEM (2 * TSTAGE * 2)     // 122880 bytes

struct R11P {
    const bf16 *A0, *A1, *A2, *A3;
    long lda;
    const bf16 *B0, *B1, *B2, *B3;
    int K;
};

__device__ __forceinline__ void r11_tload(
    uint32_t sb, int s, const R11P& p, int k0, int bm, int bn, int tid)
{
    const uint32_t st = sb + (uint32_t)(s * TSTAGE) * 2u;
    const bf16* pa[4] = { p.A0, p.A1, p.A2, p.A3 };
    const bf16* pb[4] = { p.B0, p.B1, p.B2, p.B3 };
#pragma unroll
    for (int a = 0; a < 4; a++) {
        const uint32_t base = st + (uint32_t)(a * TA_H) * 2u;
#pragma unroll
        for (int it = 0; it < 2; it++) {
            int li = tid + it * 256;
            int row = li >> 2, c8 = (li & 3) * 8;
            r11_cp16(base + (uint32_t)(row * TLD + c8) * 2u,
                     pa[a] + (long)(bm + row) * p.lda + k0 + c8);
        }
    }
#pragma unroll
    for (int a = 0; a < 4; a++) {
        const uint32_t base = st + (uint32_t)(4 * TA_H + a * TB_H) * 2u;
        int row = tid >> 2, c8 = (tid & 3) * 8;
        r11_cp16(base + (uint32_t)(row * TLD + c8) * 2u,
                 pb[a] + (long)(bn + row) * p.K + k0 + c8);
    }
    asm volatile("cp.async.commit_group;" ::: "memory");
}

__global__ void __launch_bounds__(256, 1) r11_tgemm(
    R11P p0, R11P p1, int npass, const int* gate,
    const float* __restrict__ bias1, const float* __restrict__ bias2,
    float* __restrict__ C, int ldc, float alpha)
{
    if (gate && (*(volatile const int*)gate) != 1) return;
    extern __shared__ __align__(16) bf16 sm[];
    const uint32_t sb = r11_smem_u32(sm);
    const int tid = threadIdx.x, wid = tid >> 5;
    const int bm = blockIdx.y * TBM, bn = blockIdx.x * TBN;
    const int wm = (wid & 3) * 32, wn = (wid >> 2) * 32;

    wmma::fragment<wmma::accumulator, 16, 16, 16, float> ac0[2][2], ac1[2][2], ac2[2][2];
#pragma unroll
    for (int i = 0; i < 2; i++)
#pragma unroll
        for (int j = 0; j < 2; j++) {
            wmma::fill_fragment(ac0[i][j], 0.0f);
            wmma::fill_fragment(ac1[i][j], 0.0f);
            wmma::fill_fragment(ac2[i][j], 0.0f);
        }

    const int t0 = p0.K / TBK;
    const int t1 = (npass > 1) ? (p1.K / TBK) : 0;
    const int total = t0 + t1;

    r11_tload(sb, 0, p0, 0, bm, bn, tid);

    for (int gt = 0; gt < total; gt++) {
        const int s = gt & 1;
        if (gt + 1 < total) {
            const int nt = gt + 1;
            const bool in1 = (nt >= t0);
            r11_tload(sb, s ^ 1, in1 ? p1 : p0, (in1 ? (nt - t0) : nt) * TBK,
                      bm, bn, tid);
            asm volatile("cp.async.wait_group 1;" ::: "memory");
        } else {
            asm volatile("cp.async.wait_group 0;" ::: "memory");
        }
        __syncthreads();

        const bf16* As[4];
        const bf16* Bs[4];
#pragma unroll
        for (int a = 0; a < 4; a++) {
            As[a] = sm + s * TSTAGE + a * TA_H;
            Bs[a] = sm + s * TSTAGE + 4 * TA_H + a * TB_H;
        }

#pragma unroll
        for (int kk = 0; kk < TBK / 16; kk++) {
            wmma::fragment<wmma::matrix_b, 16, 16, 16, bf16, wmma::col_major> bf[4][2];
#pragma unroll
            for (int a = 0; a < 4; a++)
#pragma unroll
                for (int j = 0; j < 2; j++)
                    wmma::load_matrix_sync(bf[a][j], Bs[a] + (wn + j * 16) * TLD + kk * 16, TLD);
#pragma unroll
            for (int i = 0; i < 2; i++) {
                wmma::fragment<wmma::matrix_a, 16, 16, 16, bf16, wmma::row_major> af[4];
#pragma unroll
                for (int a = 0; a < 4; a++)
                    wmma::load_matrix_sync(af[a], As[a] + (wm + i * 16) * TLD + kk * 16, TLD);
#pragma unroll
                for (int j = 0; j < 2; j++) {
                    wmma::mma_sync(ac0[i][j], af[0], bf[0][j], ac0[i][j]);
                    wmma::mma_sync(ac1[i][j], af[0], bf[1][j], ac1[i][j]);
                    wmma::mma_sync(ac1[i][j], af[1], bf[0][j], ac1[i][j]);
                    wmma::mma_sync(ac2[i][j], af[0], bf[2][j], ac2[i][j]);
                    wmma::mma_sync(ac2[i][j], af[1], bf[1][j], ac2[i][j]);
                    wmma::mma_sync(ac2[i][j], af[2], bf[0][j], ac2[i][j]);
                    wmma::mma_sync(ac2[i][j], af[0], bf[3][j], ac2[i][j]);
                    wmma::mma_sync(ac2[i][j], af[1], bf[2][j], ac2[i][j]);
                    wmma::mma_sync(ac2[i][j], af[2], bf[1][j], ac2[i][j]);
                    wmma::mma_sync(ac2[i][j], af[3], bf[0][j], ac2[i][j]);
                }
            }
        }
        __syncthreads();
    }

#pragma unroll
    for (int i = 0; i < 2; i++)
#pragma unroll
        for (int j = 0; j < 2; j++)
#pragma unroll
            for (int e = 0; e < ac0[i][j].num_elements; e++)
                ac0[i][j].x[e] += (ac2[i][j].x[e] + ac1[i][j].x[e]);

    float* smf = (float*)sm;
    const int LDT = TBN + 4;
    __syncthreads();
#pragma unroll
    for (int i = 0; i < 2; i++)
#pragma unroll
        for (int j = 0; j < 2; j++)
            wmma::store_matrix_sync(smf + (wm + i * 16) * LDT + wn + j * 16,
                                    ac0[i][j], LDT, wmma::mem_row_major);
    __syncthreads();

    const int row = tid >> 1;
    const int c0 = (tid & 1) * 32;
#pragma unroll
    for (int j = 0; j < 8; j++) {
        const int col = c0 + j * 4;
        float4 v = *(const float4*)(smf + row * LDT + col);
        const int gc = bn + col;
        float b0 = bias1 ? __ldg(bias1 + gc + 0) : 0.0f;
        float b1 = bias1 ? __ldg(bias1 + gc + 1) : 0.0f;
        float b2 = bias1 ? __ldg(bias1 + gc + 2) : 0.0f;
        float b3 = bias1 ? __ldg(bias1 + gc + 3) : 0.0f;
        if (bias2) {
            b0 += __ldg(bias2 + gc + 0); b1 += __ldg(bias2 + gc + 1);
            b2 += __ldg(bias2 + gc + 2); b3 += __ldg(bias2 + gc + 3);
        }
        float4 o;
        o.x = alpha * v.x + b0; o.y = alpha * v.y + b1;
        o.z = alpha * v.z + b2; o.w = alpha * v.w + b3;
        *(float4*)(C + (long)(bm + row) * ldc + gc) = o;
    }
}

// ==================== prep / check kernels ==================================
__global__ void __launch_bounds__(256) r11_split4_kernel(
    const float* __restrict__ a, bf16* __restrict__ o0, bf16* __restrict__ o1,
    bf16* __restrict__ o2, bf16* __restrict__ o3)
{
    long i = ((long)blockIdx.x * 256 + threadIdx.x) * 8;
    float4 v0 = *(const float4*)(a + i);
    float4 v1 = *(const float4*)(a + i + 4);
    float vv[8] = { v0.x, v0.y, v0.z, v0.w, v1.x, v1.y, v1.z, v1.w };
    __align__(16) bf16 q[8][4];
#pragma unroll
    for (int k = 0; k < 8; k++) r11_split4(vv[k], q[k]);
    __align__(16) bf16 t0[8], t1[8], t2[8], t3[8];
#pragma unroll
    for (int k = 0; k < 8; k++) { t0[k]=q[k][0]; t1[k]=q[k][1]; t2[k]=q[k][2]; t3[k]=q[k][3]; }
    *(uint4*)(o0 + i) = *(uint4*)t0;
    *(uint4*)(o1 + i) = *(uint4*)t1;
    *(uint4*)(o2 + i) = *(uint4*)t2;
    *(uint4*)(o3 + i) = *(uint4*)t3;
}

__global__ void __launch_bounds__(256) r11_splitT4_kernel(
    const float* __restrict__ W, bf16* __restrict__ T0, bf16* __restrict__ T1,
    bf16* __restrict__ T2, bf16* __restrict__ T3, int K, int N)
{
    __shared__ float tile[32][33];
    const int n0 = blockIdx.x * 32, k0 = blockIdx.y * 32;
    const int tx = threadIdx.x & 31, ty = threadIdx.x >> 5;
    for (int i = ty; i < 32; i += 8)
        tile[i][tx] = W[(long)(k0 + i) * N + n0 + tx];
    __syncthreads();
    for (int i = ty; i < 32; i += 8) {
        bf16 s[4];
        r11_split4(tile[tx][i], s);
        long o = (long)(n0 + i) * K + k0 + tx;
        T0[o] = s[0]; T1[o] = s[1]; T2[o] = s[2]; T3[o] = s[3];
    }
}

__global__ void __launch_bounds__(256) r11_check_kernel(
    const float* __restrict__ f, const float* __restrict__ t, int* viol, long n4)
{
    long i = (long)blockIdx.x * 256 + threadIdx.x;
    if (i >= n4) return;
    float4 a = ((const float4*)f)[i];
    float4 b = ((const float4*)t)[i];
    int bad = 0;
    bad += (fabsf(a.x - b.x) > 2e-6f * fmaxf(fabsf(a.x), 1.0f));
    bad += (fabsf(a.y - b.y) > 2e-6f * fmaxf(fabsf(a.y), 1.0f));
    bad += (fabsf(a.z - b.z) > 2e-6f * fmaxf(fabsf(a.z), 1.0f));
    bad += (fabsf(a.w - b.w) > 2e-6f * fmaxf(fabsf(a.w), 1.0f));
    if (bad) atomicAdd(viol, bad);
}

__global__ void r11_setflag_kernel(int* flag, const int* viol) {
    *flag = (*viol == 0) ? 1 : 0;
}

// ==================== elementwise step kernels ==============================
__inline__ __device__ float r11_warpsum(float v) {
#pragma unroll
    for (int o = 16; o > 0; o >>= 1) v += __shfl_xor_sync(0xffffffffu, v, o);
    return v;
}

__global__ void __launch_bounds__(256) r11_step1_kernel(
    const float* __restrict__ pre, float* __restrict__ rec,
    float* __restrict__ ctx, float* __restrict__ sfloat,
    bf16* __restrict__ s0_o, bf16* __restrict__ s1_o,
    bf16* __restrict__ s2_o, bf16* __restrict__ s3_o,
    const float* __restrict__ gamma, const float* __restrict__ beta)
{
    const int row = blockIdx.x;
    const float* p = pre + (long)row * H_;
    float* r = rec + (long)row * H_;
    float vals[8];
    float sum = 0.f, sumsq = 0.f;
#pragma unroll
    for (int i = 0; i < 8; i++) {
        int h = threadIdx.x + i * 256;
        float u = tanhf(p[h]);
        float nr = 0.9f * r[h] + 0.1f * u;
        r[h] = nr; vals[i] = nr;
        sum += nr; sumsq += nr * nr;
    }
    float w1 = r11_warpsum(sum), w2 = r11_warpsum(sumsq);
    __shared__ float sh[16];
    int warp = threadIdx.x >> 5, lane = threadIdx.x & 31;
    if (lane == 0) { sh[warp] = w1; sh[8 + warp] = w2; }
    __syncthreads();
    if (threadIdx.x == 0) {
        float a = 0.f, b = 0.f;
#pragma unroll
        for (int i = 0; i < 8; i++) { a += sh[i]; b += sh[8 + i]; }
        sh[0] = a; sh[8] = b;
    }
    __syncthreads();
    const float mean = sh[0] * (1.0f / H_);
    const float var  = sh[8] * (1.0f / H_) - mean * mean;
    const float inv  = rsqrtf(var + 1e-5f);
#pragma unroll
    for (int i = 0; i < 8; i++) {
        int h = threadIdx.x + i * 256;
        float c = (vals[i] - mean) * inv * gamma[h] + beta[h];
        long o = (long)row * H_ + h;
        ctx[o] = c;
        float s = c + vals[i];
        sfloat[o] = s;
        bf16 q[4]; r11_split4(s, q);
        s0_o[o] = q[0]; s1_o[o] = q[1]; s2_o[o] = q[2]; s3_o[o] = q[3];
    }
}

__global__ void __launch_bounds__(256) r11_step2_kernel(
    const float* __restrict__ pre, const float* __restrict__ ctx,
    const float* __restrict__ rec, float* __restrict__ gfloat,
    bf16* __restrict__ g0_o, bf16* __restrict__ g1_o,
    bf16* __restrict__ g2_o, bf16* __restrict__ g3_o)
{
    long i = ((long)blockIdx.x * 256 + threadIdx.x) * 4;
    float4 p = *(const float4*)(pre + i);
    float4 c = *(const float4*)(ctx + i);
    float4 r = *(const float4*)(rec + i);
    float pv[4] = { p.x, p.y, p.z, p.w };
    float cv[4] = { c.x, c.y, c.z, c.w };
    float rv[4] = { r.x, r.y, r.z, r.w };
    float ov[4];
    __align__(8) bf16 q0[4], q1[4], q2[4], q3[4];
#pragma unroll
    for (int k = 0; k < 4; k++) {
        float g = 1.0f / (1.0f + expf(-pv[k]));
        ov[k] = g * cv[k] + (1.0f - g) * rv[k];
        bf16 q[4]; r11_split4(ov[k], q);
        q0[k] = q[0]; q1[k] = q[1]; q2[k] = q[2]; q3[k] = q[3];
    }
    *(float4*)(gfloat + i) = make_float4(ov[0], ov[1], ov[2], ov[3]);
    *(uint2*)(g0_o + i) = *(uint2*)q0;
    *(uint2*)(g1_o + i) = *(uint2*)q1;
    *(uint2*)(g2_o + i) = *(uint2*)q2;
    *(uint2*)(g3_o + i) = *(uint2*)q3;
}

// step3: LIF + near-threshold fp64 refinement + attr double-buffer
__global__ void __launch_bounds__(256) r11_step3_kernel(
    const float* __restrict__ cur, const float* __restrict__ attr_in,
    float* __restrict__ attr_out,
    bf16* __restrict__ a0_o, bf16* __restrict__ a1_o,
    bf16* __restrict__ a2_o, bf16* __restrict__ a3_o,
    float* __restrict__ spk,
    const float* __restrict__ gf,
    const float* __restrict__ Wenc, const float* __restrict__ benc,
    const float* __restrict__ Wrec, const float* __restrict__ brec,
    int refine)
{
    long i = ((long)blockIdx.x * 256 + threadIdx.x) * 4;
    float4 c = *(const float4*)(cur + i);
    float4 a = *(const float4*)(attr_in + i);
    float4 sp = *(float4*)(spk + i);
    float cv[4] = { c.x, c.y, c.z, c.w };
    float av[4] = { a.x, a.y, a.z, a.w };
    float sv[4] = { sp.x, sp.y, sp.z, sp.w };
    __align__(8) bf16 q0[4], q1[4], q2[4], q3[4];
    const long row = i / H_;
    const int  hb  = (int)(i % H_);
#pragma unroll
    for (int k = 0; k < 4; k++) {
        float v = av[k] + (cv[k] - av[k]) * 0.5f;
        if (refine && fabsf(v - 1.0f) < 1e-3f) {
            const int h = hb + k;
            const float* grow = gf + row * H_;
            const float* arow = attr_in + row * H_;
            double acc = (double)benc[h] + (double)brec[h];
            for (int kk = 0; kk < H_; kk++) {
                acc += (double)grow[kk] * (double)Wenc[(long)kk * H_ + h];
                acc += (double)arow[kk] * (double)Wrec[(long)kk * H_ + h];
            }
            v = av[k] + ((float)acc - av[k]) * 0.5f;
        }
        float s = (v > 1.0f) ? 1.0f : 0.0f;
        av[k] = v - s; sv[k] += s;
        bf16 q[4]; r11_split4(av[k], q);
        q0[k] = q[0]; q1[k] = q[1]; q2[k] = q[2]; q3[k] = q[3];
    }
    *(float4*)(attr_out + i) = make_float4(av[0], av[1], av[2], av[3]);
    *(float4*)(spk + i)      = make_float4(sv[0], sv[1], sv[2], sv[3]);
    *(uint2*)(a0_o + i) = *(uint2*)q0;
    *(uint2*)(a1_o + i) = *(uint2*)q1;
    *(uint2*)(a2_o + i) = *(uint2*)q2;
    *(uint2*)(a3_o + i) = *(uint2*)q3;
}

__global__ void __launch_bounds__(256) r11_init_kernel(
    float* __restrict__ rec, float* __restrict__ attr, float* __restrict__ spk,
    bf16* __restrict__ a0, bf16* __restrict__ a1, bf16* __restrict__ a2,
    bf16* __restrict__ a3, int* viol)
{
    long i = (long)blockIdx.x * 256 + threadIdx.x;
    if (i == 0) *viol = 0;
    float4 z = make_float4(0.f, 0.f, 0.f, 0.f);
    ((float4*)rec)[i] = z; ((float4*)attr)[i] = z; ((float4*)spk)[i] = z;
    uint2 z2 = make_uint2(0u, 0u);
    ((uint2*)a0)[i] = z2; ((uint2*)a1)[i] = z2;
    ((uint2*)a2)[i] = z2; ((uint2*)a3)[i] = z2;
}

__global__ void __launch_bounds__(256) r11_tail_kernel(
    const float* __restrict__ rec, const float* __restrict__ attr, float* __restrict__ out)
{
    long i = (long)blockIdx.x * 256 + threadIdx.x;
    ((float4*)out)[i] = ((const float4*)rec)[i];
    ((float4*)(out + (long)B_ * H_))[i] = ((const float4*)attr)[i];
}

// ==================== launch =================================================
#define GETSYM(var, sym) cudaGetSymbolAddress((void**)&var, sym)

extern "C" void kernel_launch(void* const* d_in, const int* in_sizes, int n_in,
                              void* d_out, int out_size)
{
    const float* x    = (const float*)d_in[0];
    const float* Wp   = (const float*)d_in[1];
    const float* bp   = (const float*)d_in[2];
    const float* Wfc  = (const float*)d_in[3];
    const float* bfc  = (const float*)d_in[4];
    const float* gamma= (const float*)d_in[5];
    const float* beta = (const float*)d_in[6];
    const float* Wg   = (const float*)d_in[7];
    const float* bg   = (const float*)d_in[8];
    const float* Wenc = (const float*)d_in[9];
    const float* benc = (const float*)d_in[10];
    const float* Wrec = (const float*)d_in[11];
    const float* brec = (const float*)d_in[12];
    const float* Wro  = (const float*)d_in[13];
    const float* bro  = (const float*)d_in[14];
    float* out = (float*)d_out;

    int *flag, *viol;
    float *inp, *pre, *sf, *gf, *ctx, *rec, *attrA, *attrB, *spk, *testF, *testT;
    GETSYM(flag, r11_flag);   GETSYM(viol, r11_viol);
    GETSYM(inp, r11_inp);     GETSYM(pre, r11_pre);
    GETSYM(sf, r11_sf);       GETSYM(gf, r11_gf);
    GETSYM(ctx, r11_ctx);     GETSYM(rec, r11_rec);
    GETSYM(attrA, r11_attrA); GETSYM(attrB, r11_attrB);
    GETSYM(spk, r11_spk);
    GETSYM(testF, r11_testF); GETSYM(testT, r11_testT);

    bf16 *xb0, *xb1, *xb2, *xb3, *ib0, *ib1, *ib2, *ib3;
    bf16 *Wp0, *Wp1, *Wp2, *Wp3, *Wfc0, *Wfc1, *Wfc2, *Wfc3;
    bf16 *Wg0, *Wg1, *Wg2, *Wg3, *We0, *We1, *We2, *We3;
    bf16 *Wr0, *Wr1, *Wr2, *Wr3, *Wo0, *Wo1, *Wo2, *Wo3;
    bf16 *sb0, *sb1, *sb2, *sb3, *gb0, *gb1, *gb2, *gb3;
    bf16 *ab0, *ab1, *ab2, *ab3, *pb0, *pb1, *pb2, *pb3;
    GETSYM(xb0, r11_xb0); GETSYM(xb1, r11_xb1); GETSYM(xb2, r11_xb2); GETSYM(xb3, r11_xb3);
    GETSYM(ib0, r11_ib0); GETSYM(ib1, r11_ib1); GETSYM(ib2, r11_ib2); GETSYM(ib3, r11_ib3);
    GETSYM(Wp0, r11_Wp0); GETSYM(Wp1, r11_Wp1); GETSYM(Wp2, r11_Wp2); GETSYM(Wp3, r11_Wp3);
    GETSYM(Wfc0, r11_Wfc0); GETSYM(Wfc1, r11_Wfc1); GETSYM(Wfc2, r11_Wfc2); GETSYM(Wfc3, r11_Wfc3);
    GETSYM(Wg0, r11_Wg0); GETSYM(Wg1, r11_Wg1); GETSYM(Wg2, r11_Wg2); GETSYM(Wg3, r11_Wg3);
    GETSYM(We0, r11_We0); GETSYM(We1, r11_We1); GETSYM(We2, r11_We2); GETSYM(We3, r11_We3);
    GETSYM(Wr0, r11_Wr0); GETSYM(Wr1, r11_Wr1); GETSYM(Wr2, r11_Wr2); GETSYM(Wr3, r11_Wr3);
    GETSYM(Wo0, r11_Wo0); GETSYM(Wo1, r11_Wo1); GETSYM(Wo2, r11_Wo2); GETSYM(Wo3, r11_Wo3);
    GETSYM(sb0, r11_sb0); GETSYM(sb1, r11_sb1); GETSYM(sb2, r11_sb2); GETSYM(sb3, r11_sb3);
    GETSYM(gb0, r11_gb0); GETSYM(gb1, r11_gb1); GETSYM(gb2, r11_gb2); GETSYM(gb3, r11_gb3);
    GETSYM(ab0, r11_ab0); GETSYM(ab1, r11_ab1); GETSYM(ab2, r11_ab2); GETSYM(ab3, r11_ab3);
    GETSYM(pb0, r11_pb0); GETSYM(pb1, r11_pb1); GETSYM(pb2, r11_pb2); GETSYM(pb3, r11_pb3);

    cudaFuncSetAttribute(r11_tgemm, cudaFuncAttributeMaxDynamicSharedMemorySize, TSMEM);

    const int EW = (B_ * H_ / 4) / 256;

    r11_init_kernel<<<EW, 256>>>(rec, attrA, spk, ab0, ab1, ab2, ab3, viol);

    // splits
    r11_split4_kernel<<<(B_ * T_ * D_ / 8) / 256, 256>>>(x, xb0, xb1, xb2, xb3);
    r11_splitT4_kernel<<<dim3(H_ / 32, D_ / 32), 256>>>(Wp, Wp0, Wp1, Wp2, Wp3, D_, H_);
    r11_splitT4_kernel<<<dim3(H_ / 32, H_ / 32), 256>>>(Wfc, Wfc0, Wfc1, Wfc2, Wfc3, H_, H_);
    r11_splitT4_kernel<<<dim3(H_ / 32, H_ / 32), 256>>>(Wg, Wg0, Wg1, Wg2, Wg3, H_, H_);
    r11_splitT4_kernel<<<dim3(H_ / 32, H_ / 32), 256>>>(Wenc, We0, We1, We2, We3, H_, H_);
    r11_splitT4_kernel<<<dim3(H_ / 32, H_ / 32), 256>>>(Wrec, Wr0, Wr1, Wr2, Wr3, H_, H_);
    r11_splitT4_kernel<<<dim3(O_ / 32, H_ / 32), 256>>>(Wro, Wo0, Wo1, Wo2, Wo3, H_, O_);

    // probe: x[0:128] @ Wp both ways
    r11_sgemm<<<dim3(H_ / 128, 1), 256>>>(nullptr, x, D_, Wp, nullptr, 0, nullptr,
                                          bp, nullptr, testF, H_, 128, H_, D_, 1.0f);
    {
        R11P p = { xb0, xb1, xb2, xb3, D_, Wp0, Wp1, Wp2, Wp3, D_ };
        r11_tgemm<<<dim3(H_ / TBN, 1), 256, TSMEM>>>(p, p, 1, nullptr,
                                                     bp, nullptr, testT, H_, 1.0f);
    }
    r11_check_kernel<<<(128 * H_ / 4 + 255) / 256, 256>>>(testF, testT, viol, 128 * H_ / 4);
    r11_setflag_kernel<<<1, 1>>>(flag, viol);

    // input projection (dual)
    r11_sgemm<<<dim3(H_ / 128, (B_ * T_) / 128), 256>>>(flag, x, D_, Wp,
        nullptr, 0, nullptr, bp, nullptr, inp, H_, B_ * T_, H_, D_, 1.0f);
    {
        R11P p = { xb0, xb1, xb2, xb3, D_, Wp0, Wp1, Wp2, Wp3, D_ };
        r11_tgemm<<<dim3(H_ / TBN, (B_ * T_) / TBM), 256, TSMEM>>>(p, p, 1, flag,
                                                                   bp, nullptr, inp, H_, 1.0f);
    }
    r11_split4_kernel<<<(B_ * T_ * H_ / 8) / 256, 256>>>(inp, ib0, ib1, ib2, ib3);

    const dim3 gF(H_ / 128, B_ / 128);
    const dim3 gT(H_ / TBN, B_ / TBM);
    for (int t = 0; t < T_; t++) {
        float* attr_in  = (t & 1) ? attrB : attrA;
        float* attr_out = (t & 1) ? attrA : attrB;
        // GEMM1
        r11_sgemm<<<gF, 256>>>(flag, inp + (long)t * H_, T_ * H_, Wfc,
            nullptr, 0, nullptr, bfc, nullptr, pre, H_, B_, H_, H_, 1.0f);
        {
            R11P p = { ib0 + (long)t * H_, ib1 + (long)t * H_,
                       ib2 + (long)t * H_, ib3 + (long)t * H_,
                       (long)T_ * H_, Wfc0, Wfc1, Wfc2, Wfc3, H_ };
            r11_tgemm<<<gT, 256, TSMEM>>>(p, p, 1, flag, bfc, nullptr, pre, H_, 1.0f);
        }
        r11_step1_kernel<<<B_, 256>>>(pre, rec, ctx, sf,
                                      sb0, sb1, sb2, sb3, gamma, beta);
        // GEMM2
        r11_sgemm<<<gF, 256>>>(flag, sf, H_, Wg, nullptr, 0, nullptr,
                               bg, nullptr, pre, H_, B_, H_, H_, 1.0f);
        {
            R11P p = { sb0, sb1, sb2, sb3, H_, Wg0, Wg1, Wg2, Wg3, H_ };
            r11_tgemm<<<gT, 256, TSMEM>>>(p, p, 1, flag, bg, nullptr, pre, H_, 1.0f);
        }
        r11_step2_kernel<<<EW, 256>>>(pre, ctx, rec, gf, gb0, gb1, gb2, gb3);
        // GEMM3 dual
        r11_sgemm<<<gF, 256>>>(flag, gf, H_, Wenc, attr_in, H_, Wrec,
                               benc, brec, pre, H_, B_, H_, H_, 1.0f);
        {
            R11P pa = { gb0, gb1, gb2, gb3, H_, We0, We1, We2, We3, H_ };
            R11P pb = { ab0, ab1, ab2, ab3, H_, Wr0, Wr1, Wr2, Wr3, H_ };
            r11_tgemm<<<gT, 256, TSMEM>>>(pa, pb, 2, flag, benc, brec, pre, H_, 1.0f);
        }
        r11_step3_kernel<<<EW, 256>>>(pre, attr_in, attr_out,
                                      ab0, ab1, ab2, ab3, spk,
                                      gf, Wenc, benc, Wrec, brec, 1);
    }

    // readout (dual)
    r11_split4_kernel<<<(B_ * H_ / 8) / 256, 256>>>(spk, pb0, pb1, pb2, pb3);
    r11_sgemm<<<dim3(O_ / 128, B_ / 128), 256>>>(flag, spk, H_, Wro,
        nullptr, 0, nullptr, bro, nullptr, out, O_, B_, O_, H_, 1.0f / 16.0f);
    {
        R11P p = { pb0, pb1, pb2, pb3, H_, Wo0, Wo1, Wo2, Wo3, H_ };
        r11_tgemm<<<dim3(O_ / TBN, B_ / TBM), 256, TSMEM>>>(p, p, 1, flag,
                                                            bro, nullptr, out, O_, 1.0f / 16.0f);
    }
    // after 16 steps the final attr lives in attrA
    r11_tail_kernel<<<EW, 256>>>(rec, attrA, out + (long)B_ * O_);
}

// round 12
// speedup vs baseline: 1.2884x; 1.2884x over previous
#include <cuda_runtime.h>
#include <cuda_bf16.h>
#include <math.h>
#include <stdint.h>
#include <mma.h>

using namespace nvcuda;
typedef __nv_bfloat16 bf16;

#define B_ 1024
#define T_ 16
#define D_ 1024
#define H_ 2048
#define O_ 1024

// ==================== device globals ========================================
__device__ int   r12_flag, r12_viol;
__device__ float r12_inp[B_ * T_ * H_];
__device__ float r12_preall[B_ * T_ * H_];
__device__ float r12_pre[B_ * H_];
__device__ float r12_sf[B_ * H_];
__device__ float r12_gf[B_ * H_];
__device__ float r12_ctx[B_ * H_], r12_rec[B_ * H_];
__device__ float r12_attrA[B_ * H_], r12_attrB[B_ * H_];
__device__ float r12_spk[B_ * H_];
__device__ float r12_testF[128 * H_], r12_testT[128 * H_];

__device__ bf16 r12_xb0[B_ * T_ * D_], r12_xb1[B_ * T_ * D_], r12_xb2[B_ * T_ * D_];
__device__ bf16 r12_ib0[B_ * T_ * H_], r12_ib1[B_ * T_ * H_], r12_ib2[B_ * T_ * H_];
__device__ bf16 r12_Wp0[H_ * D_], r12_Wp1[H_ * D_], r12_Wp2[H_ * D_];
__device__ bf16 r12_Wfc0[H_ * H_], r12_Wfc1[H_ * H_], r12_Wfc2[H_ * H_];
__device__ bf16 r12_Wg0[H_ * H_], r12_Wg1[H_ * H_], r12_Wg2[H_ * H_];
__device__ bf16 r12_We0[H_ * H_], r12_We1[H_ * H_], r12_We2[H_ * H_];
__device__ bf16 r12_Wr0[H_ * H_], r12_Wr1[H_ * H_], r12_Wr2[H_ * H_];
__device__ bf16 r12_Wo0[O_ * H_], r12_Wo1[O_ * H_], r12_Wo2[O_ * H_];
__device__ bf16 r12_sb0[B_ * H_], r12_sb1[B_ * H_], r12_sb2[B_ * H_];
__device__ bf16 r12_gb0[B_ * H_], r12_gb1[B_ * H_], r12_gb2[B_ * H_];
__device__ bf16 r12_ab0[B_ * H_], r12_ab1[B_ * H_], r12_ab2[B_ * H_];
__device__ bf16 r12_pb0[B_ * H_], r12_pb1[B_ * H_], r12_pb2[B_ * H_];

// ==================== helpers ===============================================
__device__ __forceinline__ void r12_split3(float v, bf16* s) {
    s[0] = __float2bfloat16(v);
    float r = v - __bfloat162float(s[0]);
    s[1] = __float2bfloat16(r);
    r -= __bfloat162float(s[1]);
    s[2] = __float2bfloat16(r);
}
__device__ __forceinline__ uint32_t r12_smem_u32(const void* p) {
    uint32_t a;
    asm("{ .reg .u64 t; cvta.to.shared.u64 t, %1; cvt.u32.u64 %0, t; }" : "=r"(a) : "l"(p));
    return a;
}
__device__ __forceinline__ void r12_cp16(uint32_t dst, const void* src) {
    asm volatile("cp.async.cg.shared.global [%0], [%1], 16;" :: "r"(dst), "l"(src));
}

// ==================== fp32 SGEMM (proven engine, gated on flag==0) ==========
__global__ void __launch_bounds__(256) r12_sgemm(
    const int* gate,
    const float* __restrict__ A1, int lda1, const float* __restrict__ B1,
    const float* __restrict__ A2, int lda2, const float* __restrict__ B2,
    const float* __restrict__ bias1, const float* __restrict__ bias2,
    float* __restrict__ C, int ldc, int M, int N, int K, float alpha)
{
    if (gate && (*(volatile const int*)gate) != 0) return;
    const int BM = 128, BN = 128, BK = 16;
    __shared__ float As[BK][BM];
    __shared__ float Bs[BK][BN];
    const int bm = blockIdx.y * BM, bn = blockIdx.x * BN;
    const int tid = threadIdx.x, tr = tid / 16, tc = tid % 16;
    const int a_r = tid / 4, a_c = (tid % 4) * 4;
    const int b_r = tid / 32, b_c = (tid % 32) * 4;

    float acc[8][8];
#pragma unroll
    for (int i = 0; i < 8; i++)
#pragma unroll
        for (int j = 0; j < 8; j++) acc[i][j] = 0.0f;

    const int npass = (A2 != nullptr) ? 2 : 1;
    for (int pass = 0; pass < npass; pass++) {
        const float* A  = pass ? A2 : A1;
        const float* Bm = pass ? B2 : B1;
        const int lda   = pass ? lda2 : lda1;
        for (int k0 = 0; k0 < K; k0 += BK) {
#pragma unroll
            for (int i = 0; i < 2; i++) {
                int r = a_r + i * 64;
                float4 v = *(const float4*)(A + (long)(bm + r) * lda + k0 + a_c);
                As[a_c + 0][r] = v.x; As[a_c + 1][r] = v.y;
                As[a_c + 2][r] = v.z; As[a_c + 3][r] = v.w;
            }
#pragma unroll
            for (int i = 0; i < 2; i++) {
                int r = b_r + i * 8;
                float4 v = *(const float4*)(Bm + (long)(k0 + r) * N + bn + b_c);
                *(float4*)&Bs[r][b_c] = v;
            }
            __syncthreads();
#pragma unroll
            for (int kk = 0; kk < BK; kk++) {
                float4 a0 = *(const float4*)&As[kk][tr * 8];
                float4 a1 = *(const float4*)&As[kk][tr * 8 + 4];
                float4 b0 = *(const float4*)&Bs[kk][tc * 8];
                float4 b1 = *(const float4*)&Bs[kk][tc * 8 + 4];
                float a[8] = {a0.x, a0.y, a0.z, a0.w, a1.x, a1.y, a1.z, a1.w};
                float b[8] = {b0.x, b0.y, b0.z, b0.w, b1.x, b1.y, b1.z, b1.w};
#pragma unroll
                for (int i = 0; i < 8; i++)
#pragma unroll
                    for (int j = 0; j < 8; j++)
                        acc[i][j] = fmaf(a[i], b[j], acc[i][j]);
            }
            __syncthreads();
        }
    }
    const int row0 = bm + tr * 8, col0 = bn + tc * 8;
    float bias[8];
#pragma unroll
    for (int j = 0; j < 8; j++) {
        float v = bias1 ? bias1[col0 + j] : 0.0f;
        if (bias2) v += bias2[col0 + j];
        bias[j] = v;
    }
#pragma unroll
    for (int i = 0; i < 8; i++) {
        float4 o0, o1;
        o0.x = alpha * acc[i][0] + bias[0]; o0.y = alpha * acc[i][1] + bias[1];
        o0.z = alpha * acc[i][2] + bias[2]; o0.w = alpha * acc[i][3] + bias[3];
        o1.x = alpha * acc[i][4] + bias[4]; o1.y = alpha * acc[i][5] + bias[5];
        o1.z = alpha * acc[i][6] + bias[6]; o1.w = alpha * acc[i][7] + bias[7];
        *(float4*)(C + (long)(row0 + i) * ldc + col0)     = o0;
        *(float4*)(C + (long)(row0 + i) * ldc + col0 + 4) = o1;
    }
}

// ==================== bf16 3-limb / 6-term tensor GEMM ======================
// CTA 128x128, 8 warps, warp tile 64x32. Two accumulator classes:
//   ac0 = a0*b0 ; ac1 = a0b1 + a1b0 + a1b1 + a0b2 + a2b0.
#define TBM 128
#define TBN 128
#define TBK 32
#define TLD 40
#define TARR (TBM * TLD)                 // 5120 halves per limb array
#define TSTAGE (6 * TARR)                // 3 A limbs + 3 B limbs
#define TSMEM (2 * TSTAGE * 2)           // 122880 bytes

struct R12P {
    const bf16 *A0, *A1, *A2;
    long lda;
    const bf16 *B0, *B1, *B2;
    int K;
};

__device__ __forceinline__ void r12_tload(
    uint32_t sb, int s, const R12P& p, int k0, int bm, int bn, int tid)
{
    const uint32_t st = sb + (uint32_t)(s * TSTAGE) * 2u;
    const bf16* arr[6] = { p.A0, p.A1, p.A2, p.B0, p.B1, p.B2 };
#pragma unroll
    for (int a = 0; a < 6; a++) {
        const long ldg = (a < 3) ? p.lda : (long)p.K;
        const int rb = (a < 3) ? bm : bn;
        const uint32_t base = st + (uint32_t)(a * TARR) * 2u;
#pragma unroll
        for (int it = 0; it < 2; it++) {
            int li = tid + it * 256;          // 0..511
            int row = li >> 2, c8 = (li & 3) * 8;
            r12_cp16(base + (uint32_t)(row * TLD + c8) * 2u,
                     arr[a] + (long)(rb + row) * ldg + k0 + c8);
        }
    }
    asm volatile("cp.async.commit_group;" ::: "memory");
}

__global__ void __launch_bounds__(256, 1) r12_tgemm(
    R12P p0, R12P p1, int npass, const int* gate,
    const float* __restrict__ bias1, const float* __restrict__ bias2,
    float* __restrict__ C, int ldc, float alpha)
{
    if (gate && (*(volatile const int*)gate) != 1) return;
    extern __shared__ __align__(16) bf16 sm[];
    const uint32_t sb = r12_smem_u32(sm);
    const int tid = threadIdx.x, wid = tid >> 5;
    const int bm = blockIdx.y * TBM, bn = blockIdx.x * TBN;
    const int wm = (wid & 1) * 64;      // 64-row warp tile
    const int wn = (wid >> 1) * 32;     // 32-col warp tile

    wmma::fragment<wmma::accumulator, 16, 16, 16, float> ac0[4][2], ac1[4][2];
#pragma unroll
    for (int i = 0; i < 4; i++)
#pragma unroll
        for (int j = 0; j < 2; j++) {
            wmma::fill_fragment(ac0[i][j], 0.0f);
            wmma::fill_fragment(ac1[i][j], 0.0f);
        }

    const int t0 = p0.K / TBK;
    const int t1 = (npass > 1) ? (p1.K / TBK) : 0;
    const int total = t0 + t1;

    r12_tload(sb, 0, p0, 0, bm, bn, tid);

    for (int gt = 0; gt < total; gt++) {
        const int s = gt & 1;
        if (gt + 1 < total) {
            const int nt = gt + 1;
            const bool in1 = (nt >= t0);
            r12_tload(sb, s ^ 1, in1 ? p1 : p0, (in1 ? (nt - t0) : nt) * TBK,
                      bm, bn, tid);
            asm volatile("cp.async.wait_group 1;" ::: "memory");
        } else {
            asm volatile("cp.async.wait_group 0;" ::: "memory");
        }
        __syncthreads();

        const bf16* As0 = sm + s * TSTAGE;
        const bf16* As1 = As0 + TARR;
        const bf16* As2 = As0 + 2 * TARR;
        const bf16* Bs0 = As0 + 3 * TARR;
        const bf16* Bs1 = As0 + 4 * TARR;
        const bf16* Bs2 = As0 + 5 * TARR;

#pragma unroll
        for (int kk = 0; kk < TBK / 16; kk++) {
            wmma::fragment<wmma::matrix_b, 16, 16, 16, bf16, wmma::col_major> b0[2], b1[2], b2[2];
#pragma unroll
            for (int j = 0; j < 2; j++) {
                wmma::load_matrix_sync(b0[j], Bs0 + (wn + j * 16) * TLD + kk * 16, TLD);
                wmma::load_matrix_sync(b1[j], Bs1 + (wn + j * 16) * TLD + kk * 16, TLD);
                wmma::load_matrix_sync(b2[j], Bs2 + (wn + j * 16) * TLD + kk * 16, TLD);
            }
#pragma unroll
            for (int i = 0; i < 4; i++) {
                wmma::fragment<wmma::matrix_a, 16, 16, 16, bf16, wmma::row_major> a0, a1, a2;
                wmma::load_matrix_sync(a0, As0 + (wm + i * 16) * TLD + kk * 16, TLD);
                wmma::load_matrix_sync(a1, As1 + (wm + i * 16) * TLD + kk * 16, TLD);
                wmma::load_matrix_sync(a2, As2 + (wm + i * 16) * TLD + kk * 16, TLD);
#pragma unroll
                for (int j = 0; j < 2; j++) {
                    wmma::mma_sync(ac0[i][j], a0, b0[j], ac0[i][j]);
                    wmma::mma_sync(ac1[i][j], a0, b1[j], ac1[i][j]);
                    wmma::mma_sync(ac1[i][j], a1, b0[j], ac1[i][j]);
                    wmma::mma_sync(ac1[i][j], a1, b1[j], ac1[i][j]);
                    wmma::mma_sync(ac1[i][j], a0, b2[j], ac1[i][j]);
                    wmma::mma_sync(ac1[i][j], a2, b0[j], ac1[i][j]);
                }
            }
        }
        __syncthreads();
    }

#pragma unroll
    for (int i = 0; i < 4; i++)
#pragma unroll
        for (int j = 0; j < 2; j++)
#pragma unroll
            for (int e = 0; e < ac0[i][j].num_elements; e++)
                ac0[i][j].x[e] += ac1[i][j].x[e];

    float* smf = (float*)sm;
    const int LDT = TBN + 4;   // 132
    __syncthreads();
#pragma unroll
    for (int i = 0; i < 4; i++)
#pragma unroll
        for (int j = 0; j < 2; j++)
            wmma::store_matrix_sync(smf + (wm + i * 16) * LDT + wn + j * 16,
                                    ac0[i][j], LDT, wmma::mem_row_major);
    __syncthreads();

    const int row = tid >> 1;
    const int ch = (tid & 1) * 64;
#pragma unroll
    for (int j = 0; j < 16; j++) {
        const int col = ch + j * 4;
        float4 v = *(const float4*)(smf + row * LDT + col);
        const int gc = bn + col;
        float b0 = bias1 ? __ldg(bias1 + gc + 0) : 0.0f;
        float b1 = bias1 ? __ldg(bias1 + gc + 1) : 0.0f;
        float b2 = bias1 ? __ldg(bias1 + gc + 2) : 0.0f;
        float b3 = bias1 ? __ldg(bias1 + gc + 3) : 0.0f;
        if (bias2) {
            b0 += __ldg(bias2 + gc + 0); b1 += __ldg(bias2 + gc + 1);
            b2 += __ldg(bias2 + gc + 2); b3 += __ldg(bias2 + gc + 3);
        }
        float4 o;
        o.x = alpha * v.x + b0; o.y = alpha * v.y + b1;
        o.z = alpha * v.z + b2; o.w = alpha * v.w + b3;
        *(float4*)(C + (long)(bm + row) * ldc + gc) = o;
    }
}

// ==================== prep / check kernels ==================================
__global__ void __launch_bounds__(256) r12_split3_kernel(
    const float* __restrict__ a, bf16* __restrict__ o0, bf16* __restrict__ o1,
    bf16* __restrict__ o2)
{
    long i = ((long)blockIdx.x * 256 + threadIdx.x) * 8;
    float4 v0 = *(const float4*)(a + i);
    float4 v1 = *(const float4*)(a + i + 4);
    float vv[8] = { v0.x, v0.y, v0.z, v0.w, v1.x, v1.y, v1.z, v1.w };
    __align__(16) bf16 q[8][3];
#pragma unroll
    for (int k = 0; k < 8; k++) r12_split3(vv[k], q[k]);
    __align__(16) bf16 t0[8], t1[8], t2[8];
#pragma unroll
    for (int k = 0; k < 8; k++) { t0[k]=q[k][0]; t1[k]=q[k][1]; t2[k]=q[k][2]; }
    *(uint4*)(o0 + i) = *(uint4*)t0;
    *(uint4*)(o1 + i) = *(uint4*)t1;
    *(uint4*)(o2 + i) = *(uint4*)t2;
}

__global__ void __launch_bounds__(256) r12_splitT3_kernel(
    const float* __restrict__ W, bf16* __restrict__ T0, bf16* __restrict__ T1,
    bf16* __restrict__ T2, int K, int N)
{
    __shared__ float tile[32][33];
    const int n0 = blockIdx.x * 32, k0 = blockIdx.y * 32;
    const int tx = threadIdx.x & 31, ty = threadIdx.x >> 5;
    for (int i = ty; i < 32; i += 8)
        tile[i][tx] = W[(long)(k0 + i) * N + n0 + tx];
    __syncthreads();
    for (int i = ty; i < 32; i += 8) {
        bf16 s[3];
        r12_split3(tile[tx][i], s);
        long o = (long)(n0 + i) * K + k0 + tx;
        T0[o] = s[0]; T1[o] = s[1]; T2[o] = s[2];
    }
}

__global__ void __launch_bounds__(256) r12_check_kernel(
    const float* __restrict__ f, const float* __restrict__ t, int* viol, long n4)
{
    long i = (long)blockIdx.x * 256 + threadIdx.x;
    if (i >= n4) return;
    float4 a = ((const float4*)f)[i];
    float4 b = ((const float4*)t)[i];
    int bad = 0;
    bad += (fabsf(a.x - b.x) > 5e-6f * fmaxf(fabsf(a.x), 1.0f));
    bad += (fabsf(a.y - b.y) > 5e-6f * fmaxf(fabsf(a.y), 1.0f));
    bad += (fabsf(a.z - b.z) > 5e-6f * fmaxf(fabsf(a.z), 1.0f));
    bad += (fabsf(a.w - b.w) > 5e-6f * fmaxf(fabsf(a.w), 1.0f));
    if (bad) atomicAdd(viol, bad);
}

__global__ void r12_setflag_kernel(int* flag, const int* viol) {
    *flag = (*viol == 0) ? 1 : 0;
}

// ==================== elementwise step kernels ==============================
__inline__ __device__ float r12_warpsum(float v) {
#pragma unroll
    for (int o = 16; o > 0; o >>= 1) v += __shfl_xor_sync(0xffffffffu, v, o);
    return v;
}

__global__ void __launch_bounds__(256) r12_step1_kernel(
    const float* __restrict__ pre, long ldp, float* __restrict__ rec,
    float* __restrict__ ctx, float* __restrict__ sfloat,
    bf16* __restrict__ s0_o, bf16* __restrict__ s1_o, bf16* __restrict__ s2_o,
    const float* __restrict__ gamma, const float* __restrict__ beta)
{
    const int row = blockIdx.x;
    const float* p = pre + (long)row * ldp;
    float* r = rec + (long)row * H_;
    float vals[8];
    float sum = 0.f, sumsq = 0.f;
#pragma unroll
    for (int i = 0; i < 8; i++) {
        int h = threadIdx.x + i * 256;
        float u = tanhf(p[h]);
        float nr = 0.9f * r[h] + 0.1f * u;
        r[h] = nr; vals[i] = nr;
        sum += nr; sumsq += nr * nr;
    }
    float w1 = r12_warpsum(sum), w2 = r12_warpsum(sumsq);
    __shared__ float sh[16];
    int warp = threadIdx.x >> 5, lane = threadIdx.x & 31;
    if (lane == 0) { sh[warp] = w1; sh[8 + warp] = w2; }
    __syncthreads();
    if (threadIdx.x == 0) {
        float a = 0.f, b = 0.f;
#pragma unroll
        for (int i = 0; i < 8; i++) { a += sh[i]; b += sh[8 + i]; }
        sh[0] = a; sh[8] = b;
    }
    __syncthreads();
    const float mean = sh[0] * (1.0f / H_);
    const float var  = sh[8] * (1.0f / H_) - mean * mean;
    const float inv  = rsqrtf(var + 1e-5f);
#pragma unroll
    for (int i = 0; i < 8; i++) {
        int h = threadIdx.x + i * 256;
        float c = (vals[i] - mean) * inv * gamma[h] + beta[h];
        long o = (long)row * H_ + h;
        ctx[o] = c;
        float s = c + vals[i];
        sfloat[o] = s;
        bf16 q[3]; r12_split3(s, q);
        s0_o[o] = q[0]; s1_o[o] = q[1]; s2_o[o] = q[2];
    }
}

__global__ void __launch_bounds__(256) r12_step2_kernel(
    const float* __restrict__ pre, const float* __restrict__ ctx,
    const float* __restrict__ rec, float* __restrict__ gfloat,
    bf16* __restrict__ g0_o, bf16* __restrict__ g1_o, bf16* __restrict__ g2_o)
{
    long i = ((long)blockIdx.x * 256 + threadIdx.x) * 4;
    float4 p = *(const float4*)(pre + i);
    float4 c = *(const float4*)(ctx + i);
    float4 r = *(const float4*)(rec + i);
    float pv[4] = { p.x, p.y, p.z, p.w };
    float cv[4] = { c.x, c.y, c.z, c.w };
    float rv[4] = { r.x, r.y, r.z, r.w };
    float ov[4];
    __align__(8) bf16 q0[4], q1[4], q2[4];
#pragma unroll
    for (int k = 0; k < 4; k++) {
        float g = 1.0f / (1.0f + expf(-pv[k]));
        ov[k] = g * cv[k] + (1.0f - g) * rv[k];
        bf16 q[3]; r12_split3(ov[k], q);
        q0[k] = q[0]; q1[k] = q[1]; q2[k] = q[2];
    }
    *(float4*)(gfloat + i) = make_float4(ov[0], ov[1], ov[2], ov[3]);
    *(uint2*)(g0_o + i) = *(uint2*)q0;
    *(uint2*)(g1_o + i) = *(uint2*)q1;
    *(uint2*)(g2_o + i) = *(uint2*)q2;
}

__global__ void __launch_bounds__(256) r12_step3_kernel(
    const float* __restrict__ cur, const float* __restrict__ attr_in,
    float* __restrict__ attr_out,
    bf16* __restrict__ a0_o, bf16* __restrict__ a1_o, bf16* __restrict__ a2_o,
    float* __restrict__ spk,
    const float* __restrict__ gf,
    const float* __restrict__ Wenc, const float* __restrict__ benc,
    const float* __restrict__ Wrec, const float* __restrict__ brec)
{
    long i = ((long)blockIdx.x * 256 + threadIdx.x) * 4;
    float4 c = *(const float4*)(cur + i);
    float4 a = *(const float4*)(attr_in + i);
    float4 sp = *(float4*)(spk + i);
    float cv[4] = { c.x, c.y, c.z, c.w };
    float av[4] = { a.x, a.y, a.z, a.w };
    float sv[4] = { sp.x, sp.y, sp.z, sp.w };
    __align__(8) bf16 q0[4], q1[4], q2[4];
    const long row = i / H_;
    const int  hb  = (int)(i % H_);
#pragma unroll
    for (int k = 0; k < 4; k++) {
        float v = av[k] + (cv[k] - av[k]) * 0.5f;
        if (fabsf(v - 1.0f) < 1e-4f) {
            const int h = hb + k;
            const float* grow = gf + row * H_;
            const float* arow = attr_in + row * H_;
            double acc = (double)benc[h] + (double)brec[h];
            for (int kk = 0; kk < H_; kk++) {
                acc += (double)grow[kk] * (double)Wenc[(long)kk * H_ + h];
                acc += (double)arow[kk] * (double)Wrec[(long)kk * H_ + h];
            }
            v = av[k] + ((float)acc - av[k]) * 0.5f;
        }
        float s = (v > 1.0f) ? 1.0f : 0.0f;
        av[k] = v - s; sv[k] += s;
        bf16 q[3]; r12_split3(av[k], q);
        q0[k] = q[0]; q1[k] = q[1]; q2[k] = q[2];
    }
    *(float4*)(attr_out + i) = make_float4(av[0], av[1], av[2], av[3]);
    *(float4*)(spk + i)      = make_float4(sv[0], sv[1], sv[2], sv[3]);
    *(uint2*)(a0_o + i) = *(uint2*)q0;
    *(uint2*)(a1_o + i) = *(uint2*)q1;
    *(uint2*)(a2_o + i) = *(uint2*)q2;
}

__global__ void __launch_bounds__(256) r12_init_kernel(
    float* __restrict__ rec, float* __restrict__ attr, float* __restrict__ spk,
    bf16* __restrict__ a0, bf16* __restrict__ a1, bf16* __restrict__ a2, int* viol)
{
    long i = (long)blockIdx.x * 256 + threadIdx.x;
    if (i == 0) *viol = 0;
    float4 z = make_float4(0.f, 0.f, 0.f, 0.f);
    ((float4*)rec)[i] = z; ((float4*)attr)[i] = z; ((float4*)spk)[i] = z;
    uint2 z2 = make_uint2(0u, 0u);
    ((uint2*)a0)[i] = z2; ((uint2*)a1)[i] = z2; ((uint2*)a2)[i] = z2;
}

__global__ void __launch_bounds__(256) r12_tail_kernel(
    const float* __restrict__ rec, const float* __restrict__ attr, float* __restrict__ out)
{
    long i = (long)blockIdx.x * 256 + threadIdx.x;
    ((float4*)out)[i] = ((const float4*)rec)[i];
    ((float4*)(out + (long)B_ * H_))[i] = ((const float4*)attr)[i];
}

// ==================== launch =================================================
#define GETSYM(var, sym) cudaGetSymbolAddress((void**)&var, sym)

extern "C" void kernel_launch(void* const* d_in, const int* in_sizes, int n_in,
                              void* d_out, int out_size)
{
    const float* x    = (const float*)d_in[0];
    const float* Wp   = (const float*)d_in[1];
    const float* bp   = (const float*)d_in[2];
    const float* Wfc  = (const float*)d_in[3];
    const float* bfc  = (const float*)d_in[4];
    const float* gamma= (const float*)d_in[5];
    const float* beta = (const float*)d_in[6];
    const float* Wg   = (const float*)d_in[7];
    const float* bg   = (const float*)d_in[8];
    const float* Wenc = (const float*)d_in[9];
    const float* benc = (const float*)d_in[10];
    const float* Wrec = (const float*)d_in[11];
    const float* brec = (const float*)d_in[12];
    const float* Wro  = (const float*)d_in[13];
    const float* bro  = (const float*)d_in[14];
    float* out = (float*)d_out;

    int *flag, *viol;
    float *inp, *preall, *pre, *sf, *gf, *ctx, *rec, *attrA, *attrB, *spk, *testF, *testT;
    GETSYM(flag, r12_flag);   GETSYM(viol, r12_viol);
    GETSYM(inp, r12_inp);     GETSYM(preall, r12_preall);
    GETSYM(pre, r12_pre);
    GETSYM(sf, r12_sf);       GETSYM(gf, r12_gf);
    GETSYM(ctx, r12_ctx);     GETSYM(rec, r12_rec);
    GETSYM(attrA, r12_attrA); GETSYM(attrB, r12_attrB);
    GETSYM(spk, r12_spk);
    GETSYM(testF, r12_testF); GETSYM(testT, r12_testT);

    bf16 *xb0, *xb1, *xb2, *ib0, *ib1, *ib2;
    bf16 *Wp0, *Wp1, *Wp2, *Wfc0, *Wfc1, *Wfc2, *Wg0, *Wg1, *Wg2;
    bf16 *We0, *We1, *We2, *Wr0, *Wr1, *Wr2, *Wo0, *Wo1, *Wo2;
    bf16 *sb0, *sb1, *sb2, *gb0, *gb1, *gb2, *ab0, *ab1, *ab2, *pb0, *pb1, *pb2;
    GETSYM(xb0, r12_xb0); GETSYM(xb1, r12_xb1); GETSYM(xb2, r12_xb2);
    GETSYM(ib0, r12_ib0); GETSYM(ib1, r12_ib1); GETSYM(ib2, r12_ib2);
    GETSYM(Wp0, r12_Wp0); GETSYM(Wp1, r12_Wp1); GETSYM(Wp2, r12_Wp2);
    GETSYM(Wfc0, r12_Wfc0); GETSYM(Wfc1, r12_Wfc1); GETSYM(Wfc2, r12_Wfc2);
    GETSYM(Wg0, r12_Wg0); GETSYM(Wg1, r12_Wg1); GETSYM(Wg2, r12_Wg2);
    GETSYM(We0, r12_We0); GETSYM(We1, r12_We1); GETSYM(We2, r12_We2);
    GETSYM(Wr0, r12_Wr0); GETSYM(Wr1, r12_Wr1); GETSYM(Wr2, r12_Wr2);
    GETSYM(Wo0, r12_Wo0); GETSYM(Wo1, r12_Wo1); GETSYM(Wo2, r12_Wo2);
    GETSYM(sb0, r12_sb0); GETSYM(sb1, r12_sb1); GETSYM(sb2, r12_sb2);
    GETSYM(gb0, r12_gb0); GETSYM(gb1, r12_gb1); GETSYM(gb2, r12_gb2);
    GETSYM(ab0, r12_ab0); GETSYM(ab1, r12_ab1); GETSYM(ab2, r12_ab2);
    GETSYM(pb0, r12_pb0); GETSYM(pb1, r12_pb1); GETSYM(pb2, r12_pb2);

    cudaFuncSetAttribute(r12_tgemm, cudaFuncAttributeMaxDynamicSharedMemorySize, TSMEM);

    const int EW = (B_ * H_ / 4) / 256;

    r12_init_kernel<<<EW, 256>>>(rec, attrA, spk, ab0, ab1, ab2, viol);

    // splits
    r12_split3_kernel<<<(B_ * T_ * D_ / 8) / 256, 256>>>(x, xb0, xb1, xb2);
    r12_splitT3_kernel<<<dim3(H_ / 32, D_ / 32), 256>>>(Wp, Wp0, Wp1, Wp2, D_, H_);
    r12_splitT3_kernel<<<dim3(H_ / 32, H_ / 32), 256>>>(Wfc, Wfc0, Wfc1, Wfc2, H_, H_);
    r12_splitT3_kernel<<<dim3(H_ / 32, H_ / 32), 256>>>(Wg, Wg0, Wg1, Wg2, H_, H_);
    r12_splitT3_kernel<<<dim3(H_ / 32, H_ / 32), 256>>>(Wenc, We0, We1, We2, H_, H_);
    r12_splitT3_kernel<<<dim3(H_ / 32, H_ / 32), 256>>>(Wrec, Wr0, Wr1, Wr2, H_, H_);
    r12_splitT3_kernel<<<dim3(O_ / 32, H_ / 32), 256>>>(Wro, Wo0, Wo1, Wo2, H_, O_);

    // probe
    r12_sgemm<<<dim3(H_ / 128, 1), 256>>>(nullptr, x, D_, Wp, nullptr, 0, nullptr,
                                          bp, nullptr, testF, H_, 128, H_, D_, 1.0f);
    {
        R12P p = { xb0, xb1, xb2, D_, Wp0, Wp1, Wp2, D_ };
        r12_tgemm<<<dim3(H_ / TBN, 1), 256, TSMEM>>>(p, p, 1, nullptr,
                                                     bp, nullptr, testT, H_, 1.0f);
    }
    r12_check_kernel<<<(128 * H_ / 4 + 255) / 256, 256>>>(testF, testT, viol, 128 * H_ / 4);
    r12_setflag_kernel<<<1, 1>>>(flag, viol);

    // input projection (dual): inp = x @ Wp + bp  (M = B*T)
    r12_sgemm<<<dim3(H_ / 128, (B_ * T_) / 128), 256>>>(flag, x, D_, Wp,
        nullptr, 0, nullptr, bp, nullptr, inp, H_, B_ * T_, H_, D_, 1.0f);
    {
        R12P p = { xb0, xb1, xb2, D_, Wp0, Wp1, Wp2, D_ };
        r12_tgemm<<<dim3(H_ / TBN, (B_ * T_) / TBM), 256, TSMEM>>>(p, p, 1, flag,
                                                                   bp, nullptr, inp, H_, 1.0f);
    }
    r12_split3_kernel<<<(B_ * T_ * H_ / 8) / 256, 256>>>(inp, ib0, ib1, ib2);

    // batched GEMM1 for ALL timesteps (dual): preall = inp @ Wfc + bfc
    r12_sgemm<<<dim3(H_ / 128, (B_ * T_) / 128), 256>>>(flag, inp, H_, Wfc,
        nullptr, 0, nullptr, bfc, nullptr, preall, H_, B_ * T_, H_, H_, 1.0f);
    {
        R12P p = { ib0, ib1, ib2, H_, Wfc0, Wfc1, Wfc2, H_ };
        r12_tgemm<<<dim3(H_ / TBN, (B_ * T_) / TBM), 256, TSMEM>>>(p, p, 1, flag,
                                                                   bfc, nullptr, preall, H_, 1.0f);
    }

    const dim3 gF(H_ / 128, B_ / 128);
    const dim3 gT(H_ / TBN, B_ / TBM);
    for (int t = 0; t < T_; t++) {
        float* attr_in  = (t & 1) ? attrB : attrA;
        float* attr_out = (t & 1) ? attrA : attrB;
        r12_step1_kernel<<<B_, 256>>>(preall + (long)t * H_, (long)T_ * H_,
                                      rec, ctx, sf, sb0, sb1, sb2, gamma, beta);
        // GEMM2 (dual)
        r12_sgemm<<<gF, 256>>>(flag, sf, H_, Wg, nullptr, 0, nullptr,
                               bg, nullptr, pre, H_, B_, H_, H_, 1.0f);
        {
            R12P p = { sb0, sb1, sb2, H_, Wg0, Wg1, Wg2, H_ };
            r12_tgemm<<<gT, 256, TSMEM>>>(p, p, 1, flag, bg, nullptr, pre, H_, 1.0f);
        }
        r12_step2_kernel<<<EW, 256>>>(pre, ctx, rec, gf, gb0, gb1, gb2);
        // GEMM3 dual-pass (dual)
        r12_sgemm<<<gF, 256>>>(flag, gf, H_, Wenc, attr_in, H_, Wrec,
                               benc, brec, pre, H_, B_, H_, H_, 1.0f);
        {
            R12P pa = { gb0, gb1, gb2, H_, We0, We1, We2, H_ };
            R12P pb = { ab0, ab1, ab2, H_, Wr0, Wr1, Wr2, H_ };
            r12_tgemm<<<gT, 256, TSMEM>>>(pa, pb, 2, flag, benc, brec, pre, H_, 1.0f);
        }
        r12_step3_kernel<<<EW, 256>>>(pre, attr_in, attr_out,
                                      ab0, ab1, ab2, spk,
                                      gf, Wenc, benc, Wrec, brec);
    }

    // readout (dual)
    r12_split3_kernel<<<(B_ * H_ / 8) / 256, 256>>>(spk, pb0, pb1, pb2);
    r12_sgemm<<<dim3(O_ / 128, B_ / 128), 256>>>(flag, spk, H_, Wro,
        nullptr, 0, nullptr, bro, nullptr, out, O_, B_, O_, H_, 1.0f / 16.0f);
    {
        R12P p = { pb0, pb1, pb2, H_, Wo0, Wo1, Wo2, H_ };
        r12_tgemm<<<dim3(O_ / TBN, B_ / TBM), 256, TSMEM>>>(p, p, 1, flag,
                                                            bro, nullptr, out, O_, 1.0f / 16.0f);
    }
    r12_tail_kernel<<<EW, 256>>>(rec, attrA, out + (long)B_ * O_);
}